// round 4
// baseline (speedup 1.0000x reference)
#include <cuda_runtime.h>
#include <math.h>
#include <stddef.h>

// Problem dims (fixed)
constexpr int B_  = 64;
constexpr int T_  = 512;
constexpr int D_  = 512;
constexpr int H_  = 512;
constexpr int G_  = 2048;              // 4*H gates (i,f,g,o)
constexpr int BT_ = B_ * T_;           // 32768
constexpr size_t BTG_ = (size_t)BT_ * G_;   // 67108864 per direction
constexpr size_t HG_  = (size_t)H_ * G_;    // 1048576
constexpr int BH_ = B_ * H_;           // 32768

constexpr unsigned NBLK_ = 128;        // persistent grid: 64 jtiles x 2 dirs

// Scratch (device globals; no runtime allocation allowed)
__device__ float g_zx[2 * 67108864];        // [dir][B*T][G] gate preactivations
__device__ float g_h0[33554432];            // layer-0 output [B][T][2H]
__device__ float g_Ur[2 * 1048576];         // permuted recurrent weights [dir][jt][k][32]
__device__ float g_state[6 * 32768];        // [dir][h_ping,h_pong,c][B*H]

// Software grid barrier state (128 co-resident blocks)
__device__ unsigned g_bar_count = 0;
__device__ volatile unsigned g_bar_phase = 0;

__device__ __forceinline__ void grid_barrier()
{
    __syncthreads();
    if (threadIdx.x == 0) {
        unsigned gen = g_bar_phase;
        __threadfence();                       // release: order this CTA's writes
        if (atomicAdd(&g_bar_count, 1u) == NBLK_ - 1u) {
            g_bar_count = 0;
            __threadfence();
            g_bar_phase = gen + 1u;
        } else {
            while (g_bar_phase == gen) __nanosleep(64);
            __threadfence();                   // acquire
        }
    }
    __syncthreads();
}

// ---------------------------------------------------------------------------
// Classic 128x128x8 fp32 SGEMM with bias: C[M,N] = A[M,K] * W[K,N] + bias[N]
// M = B*T = 32768, N = G = 2048 fixed; K runtime (512 or 1024).
// ---------------------------------------------------------------------------
__global__ __launch_bounds__(256) void sgemm_bias_kernel(
    const float* __restrict__ Aext, int useH0,
    const float* __restrict__ W, const float* __restrict__ bias,
    int zx_slot, int K)
{
    const float* A = useH0 ? g_h0 : Aext;
    float* C = g_zx + (size_t)zx_slot * BTG_;
    const int N = G_;

    __shared__ float As[8][128];   // [k][m] (transposed)
    __shared__ float Bs[8][128];   // [k][n]

    const int tid = threadIdx.x;
    const int bm = blockIdx.y * 128;
    const int bn = blockIdx.x * 128;

    const int arow = tid >> 1;            // 0..127
    const int acol = (tid & 1) << 2;      // 0 or 4
    const int brow = tid >> 5;            // 0..7
    const int bcol = (tid & 31) << 2;     // 0..124

    const float* Ap = A + (size_t)(bm + arow) * K + acol;
    const float* Bp = W + (size_t)brow * N + bn + bcol;

    const int ty = tid >> 4;              // 0..15
    const int tx = tid & 15;              // 0..15

    float acc[8][8];
    #pragma unroll
    for (int i = 0; i < 8; i++)
        #pragma unroll
        for (int j = 0; j < 8; j++) acc[i][j] = 0.0f;

    for (int k0 = 0; k0 < K; k0 += 8) {
        float4 av = *(const float4*)Ap;
        As[acol + 0][arow] = av.x;
        As[acol + 1][arow] = av.y;
        As[acol + 2][arow] = av.z;
        As[acol + 3][arow] = av.w;
        *(float4*)&Bs[brow][bcol] = *(const float4*)Bp;
        __syncthreads();

        #pragma unroll
        for (int k = 0; k < 8; k++) {
            float a[8], b[8];
            *(float4*)&a[0] = *(const float4*)&As[k][ty * 8];
            *(float4*)&a[4] = *(const float4*)&As[k][ty * 8 + 4];
            *(float4*)&b[0] = *(const float4*)&Bs[k][tx * 8];
            *(float4*)&b[4] = *(const float4*)&Bs[k][tx * 8 + 4];
            #pragma unroll
            for (int i = 0; i < 8; i++)
                #pragma unroll
                for (int j = 0; j < 8; j++)
                    acc[i][j] += a[i] * b[j];
        }
        __syncthreads();
        Ap += 8;
        Bp += (size_t)8 * N;
    }

    float bv[8];
    #pragma unroll
    for (int j = 0; j < 8; j++) bv[j] = bias[bn + tx * 8 + j];

    #pragma unroll
    for (int i = 0; i < 8; i++) {
        float* Cp = C + (size_t)(bm + ty * 8 + i) * N + bn + tx * 8;
        float4 v0, v1;
        v0.x = acc[i][0] + bv[0]; v0.y = acc[i][1] + bv[1];
        v0.z = acc[i][2] + bv[2]; v0.w = acc[i][3] + bv[3];
        v1.x = acc[i][4] + bv[4]; v1.y = acc[i][5] + bv[5];
        v1.z = acc[i][6] + bv[6]; v1.w = acc[i][7] + bv[7];
        *(float4*)(Cp)     = v0;
        *(float4*)(Cp + 4) = v1;
    }
}

// ---------------------------------------------------------------------------
// Permute recurrent weights U[H=512][G=2048] -> g_Ur[slot][jt][k][c]
// where jt = j/8 (64 tiles), c = gate*8 + (j%8).
// ---------------------------------------------------------------------------
__global__ void permute_U_kernel(const float* __restrict__ U, int slot)
{
    int idx = blockIdx.x * 256 + threadIdx.x;    // over 512*2048 = 1048576
    int k = idx >> 11;
    int g = idx & 2047;
    int gate = g >> 9;
    int j = g & 511;
    int jt = j >> 3, jj = j & 7;
    g_Ur[(size_t)slot * HG_ + ((size_t)jt * 512 + k) * 32 + gate * 8 + jj] = U[idx];
}

__global__ void zero_state_kernel()
{
    int i = blockIdx.x * 256 + threadIdx.x;
    if (i < 6 * BH_) g_state[i] = 0.0f;
}

// ---------------------------------------------------------------------------
// Persistent recurrent kernel: all 512 timesteps of one BiLSTM layer.
// Grid (64 jtiles, 2 dirs) = 128 blocks, all co-resident; software grid
// barrier between timesteps. Each block handles all 64 batch rows x 8
// h-columns x 4 gates: z = zx[t] + h @ U, then nonlinearities + c/h update.
// h state is ping-ponged across steps.
// ---------------------------------------------------------------------------
__global__ __launch_bounds__(256) void lstm_seq_kernel(float* __restrict__ outp)
{
    const int dir = blockIdx.y;
    const int jt  = blockIdx.x;          // 0..63
    const int tid = threadIdx.x;
    const int jj  = tid & 7;             // 0..7 -> column within jtile
    const int bb  = tid >> 3;            // 0..31 -> batch rows bb, bb+32

    __shared__ float h_s[64][36];        // padded (bank-conflict free)
    __shared__ float U_s[32][36];        // [c=gate*8+jj][k], padded

    float* out = outp ? outp : g_h0;

    const float* zx_d = g_zx + (size_t)dir * BTG_;
    const float* U_d  = g_Ur + (size_t)dir * HG_ + (size_t)jt * (512 * 32);
    float* hbase = g_state + (size_t)dir * 3 * BH_;
    float* cst   = hbase + (size_t)2 * BH_;
    const int j = jt * 8 + jj;

    for (int t = 0; t < T_; t++) {
        const int tt = dir ? (T_ - 1 - t) : t;
        const float* hprev = hbase + (size_t)(t & 1) * BH_;
        float* hnext = hbase + (size_t)((t + 1) & 1) * BH_;

        float acc[2][4];
        #pragma unroll
        for (int r = 0; r < 2; r++)
            #pragma unroll
            for (int g = 0; g < 4; g++) acc[r][g] = 0.0f;

        for (int k0 = 0; k0 < H_; k0 += 32) {
            // load h tile [64 x 32] (coalesced)
            #pragma unroll
            for (int p = 0; p < 8; p++) {
                int idx = tid + p * 256;
                int b = idx >> 5, kk = idx & 31;
                h_s[b][kk] = hprev[b * H_ + k0 + kk];
            }
            // load U tile [32k x 32c], stored transposed for float4-over-k reads
            {
                int kk = tid >> 5, c = tid & 31;
                #pragma unroll
                for (int p = 0; p < 4; p++)
                    U_s[c][kk + p * 8] = U_d[(k0 + kk + p * 8) * 32 + c];
            }
            __syncthreads();

            #pragma unroll
            for (int k = 0; k < 32; k += 4) {
                float4 h0v = *(const float4*)&h_s[bb][k];
                float4 h1v = *(const float4*)&h_s[bb + 32][k];
                #pragma unroll
                for (int g = 0; g < 4; g++) {
                    float4 u = *(const float4*)&U_s[g * 8 + jj][k];
                    acc[0][g] += h0v.x * u.x;
                    acc[0][g] += h0v.y * u.y;
                    acc[0][g] += h0v.z * u.z;
                    acc[0][g] += h0v.w * u.w;
                    acc[1][g] += h1v.x * u.x;
                    acc[1][g] += h1v.y * u.y;
                    acc[1][g] += h1v.z * u.z;
                    acc[1][g] += h1v.w * u.w;
                }
            }
            __syncthreads();
        }

        #pragma unroll
        for (int r = 0; r < 2; r++) {
            int b = bb + r * 32;
            const float* zp = zx_d + ((size_t)b * T_ + tt) * G_;
            float zi = acc[r][0] + zp[0 * H_ + j];
            float zf = acc[r][1] + zp[1 * H_ + j];
            float zg = acc[r][2] + zp[2 * H_ + j];
            float zo = acc[r][3] + zp[3 * H_ + j];
            float ig = 1.0f / (1.0f + expf(-zi));
            float fg = 1.0f / (1.0f + expf(-zf));
            float gg = tanhf(zg);
            float og = 1.0f / (1.0f + expf(-zo));
            float cn = fg * cst[b * H_ + j] + ig * gg;
            float hn = og * tanhf(cn);
            cst[b * H_ + j] = cn;
            hnext[b * H_ + j] = hn;
            out[((size_t)b * T_ + tt) * (2 * H_) + dir * H_ + j] = hn;
        }

        grid_barrier();   // h(t+1) visible to all blocks before step t+1
    }
}

// ---------------------------------------------------------------------------
extern "C" void kernel_launch(void* const* d_in, const int* in_sizes, int n_in,
                              void* d_out, int out_size)
{
    (void)in_sizes; (void)n_in; (void)out_size;
    const float* x   = (const float*)d_in[0];
    const float* W0f = (const float*)d_in[1];
    const float* U0f = (const float*)d_in[2];
    const float* b0f = (const float*)d_in[3];
    const float* W0b = (const float*)d_in[4];
    const float* U0b = (const float*)d_in[5];
    const float* b0b = (const float*)d_in[6];
    const float* W1f = (const float*)d_in[7];
    const float* U1f = (const float*)d_in[8];
    const float* b1f = (const float*)d_in[9];
    const float* W1b = (const float*)d_in[10];
    const float* U1b = (const float*)d_in[11];
    const float* b1b = (const float*)d_in[12];
    float* out = (float*)d_out;

    dim3 gemmGrid(G_ / 128, BT_ / 128);   // (16, 256)
    dim3 seqGrid(64, 2);                  // 128 persistent blocks

    // ---- Phase 0: layer 0 (input = x, K = 512) ----
    sgemm_bias_kernel<<<gemmGrid, 256>>>(x, 0, W0f, b0f, /*slot=*/0, D_);
    sgemm_bias_kernel<<<gemmGrid, 256>>>(x, 0, W0b, b0b, /*slot=*/1, D_);
    permute_U_kernel<<<4096, 256>>>(U0f, 0);
    permute_U_kernel<<<4096, 256>>>(U0b, 1);
    zero_state_kernel<<<768, 256>>>();
    lstm_seq_kernel<<<seqGrid, 256>>>((float*)nullptr);   // writes g_h0

    // ---- Phase 1: layer 1 (input = g_h0, K = 1024) ----
    sgemm_bias_kernel<<<gemmGrid, 256>>>(nullptr, 1, W1f, b1f, /*slot=*/0, 2 * H_);
    sgemm_bias_kernel<<<gemmGrid, 256>>>(nullptr, 1, W1b, b1b, /*slot=*/1, 2 * H_);
    permute_U_kernel<<<4096, 256>>>(U1f, 0);
    permute_U_kernel<<<4096, 256>>>(U1b, 1);
    zero_state_kernel<<<768, 256>>>();
    lstm_seq_kernel<<<seqGrid, 256>>>(out);               // writes d_out
}

// round 7
// speedup vs baseline: 1.1416x; 1.1416x over previous
#include <cuda_runtime.h>
#include <cuda_bf16.h>
#include <math.h>
#include <stddef.h>
#include <stdint.h>

// Problem dims (fixed)
constexpr int B_  = 64;
constexpr int T_  = 512;
constexpr int D_  = 512;
constexpr int H_  = 512;
constexpr int G_  = 2048;              // 4*H gates (i,f,g,o)
constexpr int BT_ = B_ * T_;           // 32768
constexpr size_t BTG_ = (size_t)BT_ * G_;   // 67108864 per direction
constexpr size_t HG_  = (size_t)H_ * G_;    // 1048576
constexpr int BH_ = B_ * H_;           // 32768

constexpr unsigned NBLK_ = 128;        // persistent grid: 64 jtiles x 2 dirs

// Scratch (device globals; no runtime allocation allowed).
// NOTE: these symbols are referenced ONLY from device code (host-side
// references to __device__ symbols give the host shadow address — that was
// the R6 bug: split results went to HMM-mapped host memory, device arrays
// stayed zero, zx == 0, output == 0, rel_err == 1.0).
__device__ float g_zx[2 * 67108864];        // [dir][B*T][G] gate preactivations
__device__ float g_h0[33554432];            // layer-0 output [B][T][2H]
__device__ float g_Ur[2 * 1048576];         // permuted recurrent weights
__device__ float g_state[6 * 32768];        // [dir][h_ping,h_pong,c][B*H]

// bf16-split GEMM operands
__device__ __align__(16) __nv_bfloat16 g_Ahi[33554432];   // [M, K<=1024]
__device__ __align__(16) __nv_bfloat16 g_Alo[33554432];
__device__ __align__(16) __nv_bfloat16 g_Bhi[2097152];    // [N=2048, K<=1024]
__device__ __align__(16) __nv_bfloat16 g_Blo[2097152];

// Software grid barrier state (128 co-resident blocks)
__device__ unsigned g_bar_count = 0;
__device__ volatile unsigned g_bar_phase = 0;

__device__ __forceinline__ void grid_barrier()
{
    __syncthreads();
    if (threadIdx.x == 0) {
        unsigned gen = g_bar_phase;
        __threadfence();
        if (atomicAdd(&g_bar_count, 1u) == NBLK_ - 1u) {
            g_bar_count = 0;
            __threadfence();
            g_bar_phase = gen + 1u;
        } else {
            while (g_bar_phase == gen) __nanosleep(64);
            __threadfence();
        }
    }
    __syncthreads();
}

// ---------------------------------------------------------------------------
// Baseline-PTX tensor-core helpers (compute_103-safe: ldmatrix + mma.sync)
// ---------------------------------------------------------------------------
__device__ __forceinline__ uint32_t smem_u32(const void* p) {
    uint32_t a;
    asm("{ .reg .u64 t; cvta.to.shared.u64 t, %1; cvt.u32.u64 %0, t; }" : "=r"(a) : "l"(p));
    return a;
}

__device__ __forceinline__ void ldsm_x4(uint32_t& r0, uint32_t& r1,
                                        uint32_t& r2, uint32_t& r3, uint32_t addr)
{
    asm volatile("ldmatrix.sync.aligned.m8n8.x4.shared.b16 {%0,%1,%2,%3}, [%4];"
        : "=r"(r0), "=r"(r1), "=r"(r2), "=r"(r3) : "r"(addr));
}

__device__ __forceinline__ void mma_16816(float* c, const uint32_t* a,
                                          uint32_t b0, uint32_t b1)
{
    asm volatile(
        "mma.sync.aligned.m16n8k16.row.col.f32.bf16.bf16.f32 "
        "{%0,%1,%2,%3}, {%4,%5,%6,%7}, {%8,%9}, {%0,%1,%2,%3};"
        : "+f"(c[0]), "+f"(c[1]), "+f"(c[2]), "+f"(c[3])
        : "r"(a[0]), "r"(a[1]), "r"(a[2]), "r"(a[3]), "r"(b0), "r"(b1));
}

// ---------------------------------------------------------------------------
// Split fp32 -> bf16 hi/lo into g_Ahi/g_Alo (device-symbol destinations).
// srcSel: 0 = external pointer (x), 1 = g_h0.
// ---------------------------------------------------------------------------
__global__ void split_kernel(const float4* __restrict__ srcExt, int srcSel, int n4)
{
    int i = blockIdx.x * 256 + threadIdx.x;
    if (i >= n4) return;
    const float4* src = srcSel ? (const float4*)g_h0 : srcExt;
    float4 v = src[i];
    __nv_bfloat16 h0 = __float2bfloat16(v.x);
    __nv_bfloat16 h1 = __float2bfloat16(v.y);
    __nv_bfloat16 h2 = __float2bfloat16(v.z);
    __nv_bfloat16 h3 = __float2bfloat16(v.w);
    __nv_bfloat16 l0 = __float2bfloat16(v.x - __bfloat162float(h0));
    __nv_bfloat16 l1 = __float2bfloat16(v.y - __bfloat162float(h1));
    __nv_bfloat16 l2 = __float2bfloat16(v.z - __bfloat162float(h2));
    __nv_bfloat16 l3 = __float2bfloat16(v.w - __bfloat162float(h3));
    __nv_bfloat162* hp = (__nv_bfloat162*)(g_Ahi + 4 * (size_t)i);
    __nv_bfloat162* lp = (__nv_bfloat162*)(g_Alo + 4 * (size_t)i);
    hp[0] = __nv_bfloat162(h0, h1); hp[1] = __nv_bfloat162(h2, h3);
    lp[0] = __nv_bfloat162(l0, l1); lp[1] = __nv_bfloat162(l2, l3);
}

// Transpose + split W [K, N=2048] fp32 -> g_Bhi/g_Blo [N, K] bf16
__global__ void splitW_kernel(const float* __restrict__ W, int K)
{
    int idx = blockIdx.x * 256 + threadIdx.x;      // over K*2048
    if (idx >= K * G_) return;
    int k = idx >> 11;
    int n = idx & 2047;
    float v = W[idx];
    __nv_bfloat16 h = __float2bfloat16(v);
    __nv_bfloat16 l = __float2bfloat16(v - __bfloat162float(h));
    g_Bhi[(size_t)n * K + k] = h;
    g_Blo[(size_t)n * K + k] = l;
}

// ---------------------------------------------------------------------------
// mma.sync bf16-split GEMM: C[M,N] = A[M,K] * B[N,K]^T + bias, fp32.
// Block tile 128x128, BK=32, 8 warps (2x4), warp tile 64x32.
// 3 passes (hi*hi + hi*lo + lo*hi) into fp32 accumulators.
// smem rows padded to 40 bf16 (80B) -> ldmatrix row addresses conflict-free.
// ---------------------------------------------------------------------------
__device__ __forceinline__ void load_tile_bf16(
    __nv_bfloat16 (*S)[40], const __nv_bfloat16* __restrict__ g,
    int rowbase, int K, int k0, int tid)
{
    #pragma unroll
    for (int it = 0; it < 2; it++) {
        int idx = tid + it * 256;         // 0..511 granules of 16B
        int r = idx >> 2, q = idx & 3;
        uint4 v = *reinterpret_cast<const uint4*>(
            g + (size_t)(rowbase + r) * K + k0 + q * 8);
        *reinterpret_cast<uint4*>(&S[r][q * 8]) = v;
    }
}

__global__ __launch_bounds__(256) void gemm_mma_kernel(
    const float* __restrict__ bias, int zx_slot, int K)
{
    __shared__ __align__(16) __nv_bfloat16 Ahi_s[128][40];
    __shared__ __align__(16) __nv_bfloat16 Alo_s[128][40];
    __shared__ __align__(16) __nv_bfloat16 Bhi_s[128][40];
    __shared__ __align__(16) __nv_bfloat16 Blo_s[128][40];

    const int tid = threadIdx.x;
    const int wid = tid >> 5, lane = tid & 31;
    const int warp_m = wid >> 2;          // 0..1
    const int warp_n = wid & 3;           // 0..3
    const int bn = blockIdx.x * 128;
    const int bm = blockIdx.y * 128;
    float* C = g_zx + (size_t)zx_slot * BTG_;

    float acc[4][4][4];
    #pragma unroll
    for (int mt = 0; mt < 4; mt++)
        #pragma unroll
        for (int nt = 0; nt < 4; nt++)
            #pragma unroll
            for (int q = 0; q < 4; q++) acc[mt][nt][q] = 0.0f;

    // ldmatrix source addressing (within-tile row/col, element units)
    const int a_row = warp_m * 64 + (lane & 15);        // + mt*16
    const int a_col = (lane >> 4) * 8;                  // + k16
    const int b_row = warp_n * 32 + (lane & 7) + ((lane >> 4) & 1) * 8;  // + np*16
    const int b_col = ((lane >> 3) & 1) * 8;            // + k16

    const uint32_t ahi_b = smem_u32(&Ahi_s[0][0]);
    const uint32_t alo_b = smem_u32(&Alo_s[0][0]);
    const uint32_t bhi_b = smem_u32(&Bhi_s[0][0]);
    const uint32_t blo_b = smem_u32(&Blo_s[0][0]);

    for (int k0 = 0; k0 < K; k0 += 32) {
        load_tile_bf16(Ahi_s, g_Ahi, bm, K, k0, tid);
        load_tile_bf16(Alo_s, g_Alo, bm, K, k0, tid);
        load_tile_bf16(Bhi_s, g_Bhi, bn, K, k0, tid);
        load_tile_bf16(Blo_s, g_Blo, bn, K, k0, tid);
        __syncthreads();

        #pragma unroll
        for (int kk = 0; kk < 2; kk++) {
            const int k16 = kk * 16;
            uint32_t ahi[4][4], alo[4][4];
            #pragma unroll
            for (int mt = 0; mt < 4; mt++) {
                uint32_t off = (uint32_t)((a_row + mt * 16) * 40 + k16 + a_col) * 2;
                ldsm_x4(ahi[mt][0], ahi[mt][1], ahi[mt][2], ahi[mt][3], ahi_b + off);
                ldsm_x4(alo[mt][0], alo[mt][1], alo[mt][2], alo[mt][3], alo_b + off);
            }
            uint32_t bh[4][2], bl[4][2];
            #pragma unroll
            for (int np = 0; np < 2; np++) {
                uint32_t off = (uint32_t)((b_row + np * 16) * 40 + k16 + b_col) * 2;
                ldsm_x4(bh[np*2][0], bh[np*2][1], bh[np*2+1][0], bh[np*2+1][1], bhi_b + off);
                ldsm_x4(bl[np*2][0], bl[np*2][1], bl[np*2+1][0], bl[np*2+1][1], blo_b + off);
            }
            #pragma unroll
            for (int mt = 0; mt < 4; mt++)
                #pragma unroll
                for (int nt = 0; nt < 4; nt++) {
                    mma_16816(acc[mt][nt], ahi[mt], bh[nt][0], bh[nt][1]);
                    mma_16816(acc[mt][nt], ahi[mt], bl[nt][0], bl[nt][1]);
                    mma_16816(acc[mt][nt], alo[mt], bh[nt][0], bh[nt][1]);
                }
        }
        __syncthreads();
    }

    // Epilogue: c fragment (m16n8): c0,c1 -> (row + lane/4, col + 2*(lane%4));
    // c2,c3 -> row+8.
    #pragma unroll
    for (int mt = 0; mt < 4; mt++) {
        const int row0 = bm + warp_m * 64 + mt * 16 + (lane >> 2);
        #pragma unroll
        for (int nt = 0; nt < 4; nt++) {
            const int col = bn + warp_n * 32 + nt * 8 + (lane & 3) * 2;
            const float bv0 = bias[col], bv1 = bias[col + 1];
            float2 v0, v1;
            v0.x = acc[mt][nt][0] + bv0; v0.y = acc[mt][nt][1] + bv1;
            v1.x = acc[mt][nt][2] + bv0; v1.y = acc[mt][nt][3] + bv1;
            *(float2*)&C[(size_t)row0 * G_ + col]       = v0;
            *(float2*)&C[(size_t)(row0 + 8) * G_ + col] = v1;
        }
    }
}

// ---------------------------------------------------------------------------
// Permute recurrent weights U[H=512][G=2048] -> g_Ur[slot][jt][k][32]
// ---------------------------------------------------------------------------
__global__ void permute_U_kernel(const float* __restrict__ U, int slot)
{
    int idx = blockIdx.x * 256 + threadIdx.x;    // over 512*2048
    int k = idx >> 11;
    int g = idx & 2047;
    int gate = g >> 9;
    int j = g & 511;
    int jt = j >> 3, jj = j & 7;
    g_Ur[(size_t)slot * HG_ + ((size_t)jt * 512 + k) * 32 + gate * 8 + jj] = U[idx];
}

__global__ void zero_state_kernel()
{
    int i = blockIdx.x * 256 + threadIdx.x;
    if (i < 6 * BH_) g_state[i] = 0.0f;
}

// ---------------------------------------------------------------------------
// Persistent recurrent kernel (unchanged from passing R4 version)
// ---------------------------------------------------------------------------
__global__ __launch_bounds__(256) void lstm_seq_kernel(float* __restrict__ outp)
{
    const int dir = blockIdx.y;
    const int jt  = blockIdx.x;
    const int tid = threadIdx.x;
    const int jj  = tid & 7;
    const int bb  = tid >> 3;

    __shared__ float h_s[64][36];
    __shared__ float U_s[32][36];

    float* out = outp ? outp : g_h0;

    const float* zx_d = g_zx + (size_t)dir * BTG_;
    const float* U_d  = g_Ur + (size_t)dir * HG_ + (size_t)jt * (512 * 32);
    float* hbase = g_state + (size_t)dir * 3 * BH_;
    float* cst   = hbase + (size_t)2 * BH_;
    const int j = jt * 8 + jj;

    for (int t = 0; t < T_; t++) {
        const int tt = dir ? (T_ - 1 - t) : t;
        const float* hprev = hbase + (size_t)(t & 1) * BH_;
        float* hnext = hbase + (size_t)((t + 1) & 1) * BH_;

        float acc[2][4];
        #pragma unroll
        for (int r = 0; r < 2; r++)
            #pragma unroll
            for (int g = 0; g < 4; g++) acc[r][g] = 0.0f;

        for (int k0 = 0; k0 < H_; k0 += 32) {
            #pragma unroll
            for (int p = 0; p < 8; p++) {
                int idx = tid + p * 256;
                int b = idx >> 5, kk = idx & 31;
                h_s[b][kk] = hprev[b * H_ + k0 + kk];
            }
            {
                int kk = tid >> 5, c = tid & 31;
                #pragma unroll
                for (int p = 0; p < 4; p++)
                    U_s[c][kk + p * 8] = U_d[(k0 + kk + p * 8) * 32 + c];
            }
            __syncthreads();

            #pragma unroll
            for (int k = 0; k < 32; k += 4) {
                float4 h0v = *(const float4*)&h_s[bb][k];
                float4 h1v = *(const float4*)&h_s[bb + 32][k];
                #pragma unroll
                for (int g = 0; g < 4; g++) {
                    float4 u = *(const float4*)&U_s[g * 8 + jj][k];
                    acc[0][g] += h0v.x * u.x;
                    acc[0][g] += h0v.y * u.y;
                    acc[0][g] += h0v.z * u.z;
                    acc[0][g] += h0v.w * u.w;
                    acc[1][g] += h1v.x * u.x;
                    acc[1][g] += h1v.y * u.y;
                    acc[1][g] += h1v.z * u.z;
                    acc[1][g] += h1v.w * u.w;
                }
            }
            __syncthreads();
        }

        #pragma unroll
        for (int r = 0; r < 2; r++) {
            int b = bb + r * 32;
            const float* zp = zx_d + ((size_t)b * T_ + tt) * G_;
            float zi = acc[r][0] + zp[0 * H_ + j];
            float zf = acc[r][1] + zp[1 * H_ + j];
            float zg = acc[r][2] + zp[2 * H_ + j];
            float zo = acc[r][3] + zp[3 * H_ + j];
            float ig = 1.0f / (1.0f + expf(-zi));
            float fg = 1.0f / (1.0f + expf(-zf));
            float gg = tanhf(zg);
            float og = 1.0f / (1.0f + expf(-zo));
            float cn = fg * cst[b * H_ + j] + ig * gg;
            float hn = og * tanhf(cn);
            cst[b * H_ + j] = cn;
            hnext[b * H_ + j] = hn;
            out[((size_t)b * T_ + tt) * (2 * H_) + dir * H_ + j] = hn;
        }

        grid_barrier();
    }
}

// ---------------------------------------------------------------------------
extern "C" void kernel_launch(void* const* d_in, const int* in_sizes, int n_in,
                              void* d_out, int out_size)
{
    (void)in_sizes; (void)n_in; (void)out_size;
    const float* x   = (const float*)d_in[0];
    const float* W0f = (const float*)d_in[1];
    const float* U0f = (const float*)d_in[2];
    const float* b0f = (const float*)d_in[3];
    const float* W0b = (const float*)d_in[4];
    const float* U0b = (const float*)d_in[5];
    const float* b0b = (const float*)d_in[6];
    const float* W1f = (const float*)d_in[7];
    const float* U1f = (const float*)d_in[8];
    const float* b1f = (const float*)d_in[9];
    const float* W1b = (const float*)d_in[10];
    const float* U1b = (const float*)d_in[11];
    const float* b1b = (const float*)d_in[12];
    float* out = (float*)d_out;

    dim3 gemmGrid(G_ / 128, BT_ / 128);   // (16, 256)
    dim3 seqGrid(64, 2);

    // ---- Phase 0: layer 0 (input = x, K = 512) ----
    {
        const int n4 = (BT_ * D_) / 4;
        split_kernel<<<(n4 + 255) / 256, 256>>>((const float4*)x, /*srcSel=*/0, n4);
        splitW_kernel<<<(D_ * G_ + 255) / 256, 256>>>(W0f, D_);
        gemm_mma_kernel<<<gemmGrid, 256>>>(b0f, 0, D_);
        splitW_kernel<<<(D_ * G_ + 255) / 256, 256>>>(W0b, D_);
        gemm_mma_kernel<<<gemmGrid, 256>>>(b0b, 1, D_);
        permute_U_kernel<<<4096, 256>>>(U0f, 0);
        permute_U_kernel<<<4096, 256>>>(U0b, 1);
        zero_state_kernel<<<768, 256>>>();
        lstm_seq_kernel<<<seqGrid, 256>>>((float*)nullptr);    // writes g_h0
    }

    // ---- Phase 1: layer 1 (input = g_h0, K = 1024) ----
    {
        const int K1 = 2 * H_;
        const int n4 = (BT_ * K1) / 4;
        split_kernel<<<(n4 + 255) / 256, 256>>>((const float4*)nullptr, /*srcSel=*/1, n4);
        splitW_kernel<<<(K1 * G_ + 255) / 256, 256>>>(W1f, K1);
        gemm_mma_kernel<<<gemmGrid, 256>>>(b1f, 0, K1);
        splitW_kernel<<<(K1 * G_ + 255) / 256, 256>>>(W1b, K1);
        gemm_mma_kernel<<<gemmGrid, 256>>>(b1b, 1, K1);
        permute_U_kernel<<<4096, 256>>>(U1f, 0);
        permute_U_kernel<<<4096, 256>>>(U1b, 1);
        zero_state_kernel<<<768, 256>>>();
        lstm_seq_kernel<<<seqGrid, 256>>>(out);                // writes d_out
    }
}

// round 8
// speedup vs baseline: 1.2344x; 1.0813x over previous
#include <cuda_runtime.h>
#include <cuda_bf16.h>
#include <math.h>
#include <stddef.h>
#include <stdint.h>

// Problem dims (fixed)
constexpr int B_  = 64;
constexpr int T_  = 512;
constexpr int D_  = 512;
constexpr int H_  = 512;
constexpr int G_  = 2048;              // 4*H gates (i,f,g,o)
constexpr int BT_ = B_ * T_;           // 32768
constexpr size_t BTG_ = (size_t)BT_ * G_;   // 67108864 per direction
constexpr size_t HG_  = (size_t)H_ * G_;    // 1048576
constexpr int BH_ = B_ * H_;           // 32768

constexpr unsigned NBLK_ = 128;        // persistent grid: 64 jtiles x 2 dirs

// Scratch (device globals; referenced ONLY from device code — host-side
// references to __device__ symbols give the host shadow address, the R6 bug).
__device__ float g_zx[2 * 67108864];        // [dir][B*T][G] gate preactivations
__device__ float g_h0[33554432];            // layer-0 output [B][T][2H]
__device__ float g_Ur[2 * 1048576];         // permuted recurrent weights
__device__ float g_state[6 * 32768];        // [dir][h_ping,h_pong,c][B*H]

// bf16-split GEMM operands
__device__ __align__(16) __nv_bfloat16 g_Ahi[33554432];   // [M, K<=1024]
__device__ __align__(16) __nv_bfloat16 g_Alo[33554432];
__device__ __align__(16) __nv_bfloat16 g_Bhi[2097152];    // [N=2048, K<=1024]
__device__ __align__(16) __nv_bfloat16 g_Blo[2097152];

// Software grid barrier state (128 co-resident blocks)
__device__ unsigned g_bar_count = 0;
__device__ volatile unsigned g_bar_phase = 0;

__device__ __forceinline__ void grid_barrier()
{
    __syncthreads();
    if (threadIdx.x == 0) {
        unsigned gen = g_bar_phase;
        __threadfence();
        if (atomicAdd(&g_bar_count, 1u) == NBLK_ - 1u) {
            g_bar_count = 0;
            __threadfence();
            g_bar_phase = gen + 1u;
        } else {
            while (g_bar_phase == gen) __nanosleep(64);
            __threadfence();
        }
    }
    __syncthreads();
}

// ---------------------------------------------------------------------------
// Baseline-PTX helpers (compute_103-safe: ldmatrix + mma.sync + cp.async)
// ---------------------------------------------------------------------------
__device__ __forceinline__ uint32_t smem_u32(const void* p) {
    uint32_t a;
    asm("{ .reg .u64 t; cvta.to.shared.u64 t, %1; cvt.u32.u64 %0, t; }" : "=r"(a) : "l"(p));
    return a;
}

__device__ __forceinline__ void ldsm_x4(uint32_t& r0, uint32_t& r1,
                                        uint32_t& r2, uint32_t& r3, uint32_t addr)
{
    asm volatile("ldmatrix.sync.aligned.m8n8.x4.shared.b16 {%0,%1,%2,%3}, [%4];"
        : "=r"(r0), "=r"(r1), "=r"(r2), "=r"(r3) : "r"(addr));
}

__device__ __forceinline__ void mma_16816(float* c, const uint32_t* a,
                                          uint32_t b0, uint32_t b1)
{
    asm volatile(
        "mma.sync.aligned.m16n8k16.row.col.f32.bf16.bf16.f32 "
        "{%0,%1,%2,%3}, {%4,%5,%6,%7}, {%8,%9}, {%0,%1,%2,%3};"
        : "+f"(c[0]), "+f"(c[1]), "+f"(c[2]), "+f"(c[3])
        : "r"(a[0]), "r"(a[1]), "r"(a[2]), "r"(a[3]), "r"(b0), "r"(b1));
}

__device__ __forceinline__ void cp_async16(uint32_t dst, const void* src) {
    asm volatile("cp.async.cg.shared.global [%0], [%1], 16;" :: "r"(dst), "l"(src));
}
__device__ __forceinline__ void cp_commit() {
    asm volatile("cp.async.commit_group;" ::: "memory");
}
template <int N>
__device__ __forceinline__ void cp_wait() {
    asm volatile("cp.async.wait_group %0;" :: "n"(N) : "memory");
}

// ---------------------------------------------------------------------------
// Split fp32 -> bf16 hi/lo into g_Ahi/g_Alo. srcSel: 0 = ext ptr, 1 = g_h0.
// ---------------------------------------------------------------------------
__global__ void split_kernel(const float4* __restrict__ srcExt, int srcSel, int n4)
{
    int i = blockIdx.x * 256 + threadIdx.x;
    if (i >= n4) return;
    const float4* src = srcSel ? (const float4*)g_h0 : srcExt;
    float4 v = src[i];
    __nv_bfloat16 h0 = __float2bfloat16(v.x);
    __nv_bfloat16 h1 = __float2bfloat16(v.y);
    __nv_bfloat16 h2 = __float2bfloat16(v.z);
    __nv_bfloat16 h3 = __float2bfloat16(v.w);
    __nv_bfloat16 l0 = __float2bfloat16(v.x - __bfloat162float(h0));
    __nv_bfloat16 l1 = __float2bfloat16(v.y - __bfloat162float(h1));
    __nv_bfloat16 l2 = __float2bfloat16(v.z - __bfloat162float(h2));
    __nv_bfloat16 l3 = __float2bfloat16(v.w - __bfloat162float(h3));
    __nv_bfloat162* hp = (__nv_bfloat162*)(g_Ahi + 4 * (size_t)i);
    __nv_bfloat162* lp = (__nv_bfloat162*)(g_Alo + 4 * (size_t)i);
    hp[0] = __nv_bfloat162(h0, h1); hp[1] = __nv_bfloat162(h2, h3);
    lp[0] = __nv_bfloat162(l0, l1); lp[1] = __nv_bfloat162(l2, l3);
}

// Transpose + split W [K, N=2048] fp32 -> g_Bhi/g_Blo [N, K] bf16
__global__ void splitW_kernel(const float* __restrict__ W, int K)
{
    int idx = blockIdx.x * 256 + threadIdx.x;      // over K*2048
    if (idx >= K * G_) return;
    int k = idx >> 11;
    int n = idx & 2047;
    float v = W[idx];
    __nv_bfloat16 h = __float2bfloat16(v);
    __nv_bfloat16 l = __float2bfloat16(v - __bfloat162float(h));
    g_Bhi[(size_t)n * K + k] = h;
    g_Blo[(size_t)n * K + k] = l;
}

// ---------------------------------------------------------------------------
// cp.async double-buffered mma.sync bf16-split GEMM:
// C[M,N] = A[M,K] * B[N,K]^T + bias, fp32. Block tile 128x128, BK=32,
// 8 warps (2x4), warp tile 64x32. 3 passes (hh + hl + lh).
// Dynamic smem: 2 stages x 4 tiles x (128 rows x 40 bf16 = 80B rows).
// ---------------------------------------------------------------------------
constexpr int TILE_B   = 128 * 80;        // 10240 bytes per tile
constexpr int STAGE_B  = 4 * TILE_B;      // 40960
constexpr int GEMM_SMEM_B = 2 * STAGE_B;  // 81920

__device__ __forceinline__ void stage_loads(
    uint32_t sbase, int bm, int bn, int K, int k0, int tid)
{
    #pragma unroll
    for (int it = 0; it < 2; it++) {
        int idx = tid + it * 256;          // 0..511 granules of 16B per tile
        int r = idx >> 2, q = idx & 3;
        uint32_t d = sbase + (uint32_t)(r * 80 + q * 16);
        size_t goffA = (size_t)(bm + r) * K + k0 + q * 8;
        size_t goffB = (size_t)(bn + r) * K + k0 + q * 8;
        cp_async16(d + 0 * TILE_B, g_Ahi + goffA);
        cp_async16(d + 1 * TILE_B, g_Alo + goffA);
        cp_async16(d + 2 * TILE_B, g_Bhi + goffB);
        cp_async16(d + 3 * TILE_B, g_Blo + goffB);
    }
}

__global__ __launch_bounds__(256) void gemm_mma_kernel(
    const float* __restrict__ bias, int zx_slot, int K)
{
    extern __shared__ char dsm[];
    const uint32_t sb = smem_u32(dsm);

    const int tid = threadIdx.x;
    const int wid = tid >> 5, lane = tid & 31;
    const int warp_m = wid >> 2;          // 0..1
    const int warp_n = wid & 3;           // 0..3
    const int bn = blockIdx.x * 128;
    const int bm = blockIdx.y * 128;
    float* C = g_zx + (size_t)zx_slot * BTG_;

    float acc[4][4][4];
    #pragma unroll
    for (int mt = 0; mt < 4; mt++)
        #pragma unroll
        for (int nt = 0; nt < 4; nt++)
            #pragma unroll
            for (int q = 0; q < 4; q++) acc[mt][nt][q] = 0.0f;

    // ldmatrix source addressing (within-tile row/col, element units)
    const int a_row = warp_m * 64 + (lane & 15);        // + mt*16
    const int a_col = (lane >> 4) * 8;                  // + k16
    const int b_row = warp_n * 32 + (lane & 7) + ((lane >> 4) & 1) * 8;  // + np*16
    const int b_col = ((lane >> 3) & 1) * 8;            // + k16

    const int nchunk = K / 32;

    // Prefetch stage 0
    stage_loads(sb, bm, bn, K, 0, tid);
    cp_commit();

    for (int ch = 0; ch < nchunk; ch++) {
        if (ch + 1 < nchunk) {
            stage_loads(sb + ((ch + 1) & 1) * STAGE_B, bm, bn, K, (ch + 1) * 32, tid);
            cp_commit();
            cp_wait<1>();        // stage ch complete (next stage still pending)
        } else {
            cp_wait<0>();
        }
        __syncthreads();

        const uint32_t stg = sb + (ch & 1) * STAGE_B;
        const uint32_t ahi_b = stg;
        const uint32_t alo_b = stg + 1 * TILE_B;
        const uint32_t bhi_b = stg + 2 * TILE_B;
        const uint32_t blo_b = stg + 3 * TILE_B;

        #pragma unroll
        for (int kk = 0; kk < 2; kk++) {
            const int k16 = kk * 16;
            uint32_t ahi[4][4], alo[4][4];
            #pragma unroll
            for (int mt = 0; mt < 4; mt++) {
                uint32_t off = (uint32_t)((a_row + mt * 16) * 40 + k16 + a_col) * 2;
                ldsm_x4(ahi[mt][0], ahi[mt][1], ahi[mt][2], ahi[mt][3], ahi_b + off);
                ldsm_x4(alo[mt][0], alo[mt][1], alo[mt][2], alo[mt][3], alo_b + off);
            }
            uint32_t bh[4][2], bl[4][2];
            #pragma unroll
            for (int np = 0; np < 2; np++) {
                uint32_t off = (uint32_t)((b_row + np * 16) * 40 + k16 + b_col) * 2;
                ldsm_x4(bh[np*2][0], bh[np*2][1], bh[np*2+1][0], bh[np*2+1][1], bhi_b + off);
                ldsm_x4(bl[np*2][0], bl[np*2][1], bl[np*2+1][0], bl[np*2+1][1], blo_b + off);
            }
            #pragma unroll
            for (int mt = 0; mt < 4; mt++)
                #pragma unroll
                for (int nt = 0; nt < 4; nt++) {
                    mma_16816(acc[mt][nt], ahi[mt], bh[nt][0], bh[nt][1]);
                    mma_16816(acc[mt][nt], ahi[mt], bl[nt][0], bl[nt][1]);
                    mma_16816(acc[mt][nt], alo[mt], bh[nt][0], bh[nt][1]);
                }
        }
        __syncthreads();
    }

    // Epilogue: c fragment (m16n8): c0,c1 -> (row + lane/4, col + 2*(lane%4));
    // c2,c3 -> row+8.
    #pragma unroll
    for (int mt = 0; mt < 4; mt++) {
        const int row0 = bm + warp_m * 64 + mt * 16 + (lane >> 2);
        #pragma unroll
        for (int nt = 0; nt < 4; nt++) {
            const int col = bn + warp_n * 32 + nt * 8 + (lane & 3) * 2;
            const float bv0 = bias[col], bv1 = bias[col + 1];
            float2 v0, v1;
            v0.x = acc[mt][nt][0] + bv0; v0.y = acc[mt][nt][1] + bv1;
            v1.x = acc[mt][nt][2] + bv0; v1.y = acc[mt][nt][3] + bv1;
            *(float2*)&C[(size_t)row0 * G_ + col]       = v0;
            *(float2*)&C[(size_t)(row0 + 8) * G_ + col] = v1;
        }
    }
}

// ---------------------------------------------------------------------------
// Permute recurrent weights U[H=512][G=2048] -> g_Ur[slot][jt][k][32]
// ---------------------------------------------------------------------------
__global__ void permute_U_kernel(const float* __restrict__ U, int slot)
{
    int idx = blockIdx.x * 256 + threadIdx.x;    // over 512*2048
    int k = idx >> 11;
    int g = idx & 2047;
    int gate = g >> 9;
    int j = g & 511;
    int jt = j >> 3, jj = j & 7;
    g_Ur[(size_t)slot * HG_ + ((size_t)jt * 512 + k) * 32 + gate * 8 + jj] = U[idx];
}

__global__ void zero_state_kernel()
{
    int i = blockIdx.x * 256 + threadIdx.x;
    if (i < 6 * BH_) g_state[i] = 0.0f;
}

// ---------------------------------------------------------------------------
// Persistent recurrent kernel (unchanged — known good)
// ---------------------------------------------------------------------------
__global__ __launch_bounds__(256) void lstm_seq_kernel(float* __restrict__ outp)
{
    const int dir = blockIdx.y;
    const int jt  = blockIdx.x;
    const int tid = threadIdx.x;
    const int jj  = tid & 7;
    const int bb  = tid >> 3;

    __shared__ float h_s[64][36];
    __shared__ float U_s[32][36];

    float* out = outp ? outp : g_h0;

    const float* zx_d = g_zx + (size_t)dir * BTG_;
    const float* U_d  = g_Ur + (size_t)dir * HG_ + (size_t)jt * (512 * 32);
    float* hbase = g_state + (size_t)dir * 3 * BH_;
    float* cst   = hbase + (size_t)2 * BH_;
    const int j = jt * 8 + jj;

    for (int t = 0; t < T_; t++) {
        const int tt = dir ? (T_ - 1 - t) : t;
        const float* hprev = hbase + (size_t)(t & 1) * BH_;
        float* hnext = hbase + (size_t)((t + 1) & 1) * BH_;

        float acc[2][4];
        #pragma unroll
        for (int r = 0; r < 2; r++)
            #pragma unroll
            for (int g = 0; g < 4; g++) acc[r][g] = 0.0f;

        for (int k0 = 0; k0 < H_; k0 += 32) {
            #pragma unroll
            for (int p = 0; p < 8; p++) {
                int idx = tid + p * 256;
                int b = idx >> 5, kk = idx & 31;
                h_s[b][kk] = hprev[b * H_ + k0 + kk];
            }
            {
                int kk = tid >> 5, c = tid & 31;
                #pragma unroll
                for (int p = 0; p < 4; p++)
                    U_s[c][kk + p * 8] = U_d[(k0 + kk + p * 8) * 32 + c];
            }
            __syncthreads();

            #pragma unroll
            for (int k = 0; k < 32; k += 4) {
                float4 h0v = *(const float4*)&h_s[bb][k];
                float4 h1v = *(const float4*)&h_s[bb + 32][k];
                #pragma unroll
                for (int g = 0; g < 4; g++) {
                    float4 u = *(const float4*)&U_s[g * 8 + jj][k];
                    acc[0][g] += h0v.x * u.x;
                    acc[0][g] += h0v.y * u.y;
                    acc[0][g] += h0v.z * u.z;
                    acc[0][g] += h0v.w * u.w;
                    acc[1][g] += h1v.x * u.x;
                    acc[1][g] += h1v.y * u.y;
                    acc[1][g] += h1v.z * u.z;
                    acc[1][g] += h1v.w * u.w;
                }
            }
            __syncthreads();
        }

        #pragma unroll
        for (int r = 0; r < 2; r++) {
            int b = bb + r * 32;
            const float* zp = zx_d + ((size_t)b * T_ + tt) * G_;
            float zi = acc[r][0] + zp[0 * H_ + j];
            float zf = acc[r][1] + zp[1 * H_ + j];
            float zg = acc[r][2] + zp[2 * H_ + j];
            float zo = acc[r][3] + zp[3 * H_ + j];
            float ig = 1.0f / (1.0f + expf(-zi));
            float fg = 1.0f / (1.0f + expf(-zf));
            float gg = tanhf(zg);
            float og = 1.0f / (1.0f + expf(-zo));
            float cn = fg * cst[b * H_ + j] + ig * gg;
            float hn = og * tanhf(cn);
            cst[b * H_ + j] = cn;
            hnext[b * H_ + j] = hn;
            out[((size_t)b * T_ + tt) * (2 * H_) + dir * H_ + j] = hn;
        }

        grid_barrier();
    }
}

// ---------------------------------------------------------------------------
extern "C" void kernel_launch(void* const* d_in, const int* in_sizes, int n_in,
                              void* d_out, int out_size)
{
    (void)in_sizes; (void)n_in; (void)out_size;
    const float* x   = (const float*)d_in[0];
    const float* W0f = (const float*)d_in[1];
    const float* U0f = (const float*)d_in[2];
    const float* b0f = (const float*)d_in[3];
    const float* W0b = (const float*)d_in[4];
    const float* U0b = (const float*)d_in[5];
    const float* b0b = (const float*)d_in[6];
    const float* W1f = (const float*)d_in[7];
    const float* U1f = (const float*)d_in[8];
    const float* b1f = (const float*)d_in[9];
    const float* W1b = (const float*)d_in[10];
    const float* U1b = (const float*)d_in[11];
    const float* b1b = (const float*)d_in[12];
    float* out = (float*)d_out;

    // Opt-in to 80KB dynamic smem (idempotent; no allocation, not stream-ordered)
    cudaFuncSetAttribute(gemm_mma_kernel,
                         cudaFuncAttributeMaxDynamicSharedMemorySize, GEMM_SMEM_B);

    dim3 gemmGrid(G_ / 128, BT_ / 128);   // (16, 256)
    dim3 seqGrid(64, 2);

    // ---- Phase 0: layer 0 (input = x, K = 512) ----
    {
        const int n4 = (BT_ * D_) / 4;
        split_kernel<<<(n4 + 255) / 256, 256>>>((const float4*)x, /*srcSel=*/0, n4);
        splitW_kernel<<<(D_ * G_ + 255) / 256, 256>>>(W0f, D_);
        gemm_mma_kernel<<<gemmGrid, 256, GEMM_SMEM_B>>>(b0f, 0, D_);
        splitW_kernel<<<(D_ * G_ + 255) / 256, 256>>>(W0b, D_);
        gemm_mma_kernel<<<gemmGrid, 256, GEMM_SMEM_B>>>(b0b, 1, D_);
        permute_U_kernel<<<4096, 256>>>(U0f, 0);
        permute_U_kernel<<<4096, 256>>>(U0b, 1);
        zero_state_kernel<<<768, 256>>>();
        lstm_seq_kernel<<<seqGrid, 256>>>((float*)nullptr);    // writes g_h0
    }

    // ---- Phase 1: layer 1 (input = g_h0, K = 1024) ----
    {
        const int K1 = 2 * H_;
        const int n4 = (BT_ * K1) / 4;
        split_kernel<<<(n4 + 255) / 256, 256>>>((const float4*)nullptr, /*srcSel=*/1, n4);
        splitW_kernel<<<(K1 * G_ + 255) / 256, 256>>>(W1f, K1);
        gemm_mma_kernel<<<gemmGrid, 256, GEMM_SMEM_B>>>(b1f, 0, K1);
        splitW_kernel<<<(K1 * G_ + 255) / 256, 256>>>(W1b, K1);
        gemm_mma_kernel<<<gemmGrid, 256, GEMM_SMEM_B>>>(b1b, 1, K1);
        permute_U_kernel<<<4096, 256>>>(U1f, 0);
        permute_U_kernel<<<4096, 256>>>(U1b, 1);
        zero_state_kernel<<<768, 256>>>();
        lstm_seq_kernel<<<seqGrid, 256>>>(out);                // writes d_out
    }
}